// round 2
// baseline (speedup 1.0000x reference)
#include <cuda_runtime.h>
#include <cstdint>

// Blockwise int4-dequant GEMM: out[m,n] = sum_k A[m,k] * (Q[n,k]-zp[n,k/64])*s[n,k/64] + bias[n]
// A: [M,K] f32 row-major; Q: [N,K] int32 (values 0..15); S/Z: [N, K/64]; out: [M,N] f32.
//
// Round-0 baseline: classic smem-tiled fp32 GEMM, 128x128 CTA tile, BK=16,
// 256 threads, 8x8 per-thread micro-tile, fused dequant on the W-tile load.
// BK=16 divides the 64-wide quant block, so one (scale,zp) per row per K-tile.

#define BM 128
#define BN 128
#define BK 16
#define TM 8
#define TN 8

__global__ __launch_bounds__(256, 2)
void blkq4_gemm_kernel(const float* __restrict__ A,
                       const int*   __restrict__ Q,
                       const float* __restrict__ S,
                       const int*   __restrict__ Z,
                       const float* __restrict__ bias,
                       float* __restrict__ C,
                       int M, int N, int K, int NB)
{
    __shared__ float As[BK][BM];
    __shared__ float Ws[BK][BN];

    const int tid = threadIdx.x;
    const int bn  = blockIdx.x;   // N tile
    const int bm  = blockIdx.y;   // M tile
    const int tx  = tid & 15;     // 0..15 -> N
    const int ty  = tid >> 4;     // 0..15 -> M

    const float* Ablk = A + (size_t)bm * BM * K;
    const int*   Qblk = Q + (size_t)bn * BN * K;

    float acc[TM][TN];
    #pragma unroll
    for (int i = 0; i < TM; i++)
        #pragma unroll
        for (int j = 0; j < TN; j++) acc[i][j] = 0.0f;

    for (int k0 = 0; k0 < K; k0 += BK) {
        const int kb = k0 >> 6;  // quant-block index, constant across this K-tile

        // ---- load A tile (128x16 f32), store transposed As[k][m] ----
        #pragma unroll
        for (int i = 0; i < 2; i++) {
            int id = tid + i * 256;          // 0..511 float4 slots
            int r  = id >> 2;                // row within tile (0..127)
            int c4 = (id & 3) << 2;          // col within tile (0,4,8,12)
            float4 v = *(const float4*)(Ablk + (size_t)r * K + k0 + c4);
            As[c4 + 0][r] = v.x;
            As[c4 + 1][r] = v.y;
            As[c4 + 2][r] = v.z;
            As[c4 + 3][r] = v.w;
        }

        // ---- load W tile (128x16 int32), dequant, store transposed Ws[k][n] ----
        #pragma unroll
        for (int i = 0; i < 2; i++) {
            int id = tid + i * 256;
            int r  = id >> 2;
            int c4 = (id & 3) << 2;
            int4 q = *(const int4*)(Qblk + (size_t)r * K + k0 + c4);
            int gn = bn * BN + r;
            float s  = S[(size_t)gn * NB + kb];
            float zp = (float)Z[(size_t)gn * NB + kb];
            Ws[c4 + 0][r] = ((float)q.x - zp) * s;
            Ws[c4 + 1][r] = ((float)q.y - zp) * s;
            Ws[c4 + 2][r] = ((float)q.z - zp) * s;
            Ws[c4 + 3][r] = ((float)q.w - zp) * s;
        }

        __syncthreads();

        // ---- compute: 16 k-steps, 8x8 per thread ----
        #pragma unroll
        for (int k = 0; k < BK; k++) {
            float af[TM], bf[TN];
            #pragma unroll
            for (int i = 0; i < TM; i += 4) {
                float4 v = *(const float4*)(&As[k][ty * TM + i]);
                af[i + 0] = v.x; af[i + 1] = v.y; af[i + 2] = v.z; af[i + 3] = v.w;
            }
            #pragma unroll
            for (int j = 0; j < TN; j += 4) {
                float4 v = *(const float4*)(&Ws[k][tx * TN + j]);
                bf[j + 0] = v.x; bf[j + 1] = v.y; bf[j + 2] = v.z; bf[j + 3] = v.w;
            }
            #pragma unroll
            for (int i = 0; i < TM; i++)
                #pragma unroll
                for (int j = 0; j < TN; j++)
                    acc[i][j] = fmaf(af[i], bf[j], acc[i][j]);
        }

        __syncthreads();
    }

    // ---- epilogue: add bias, vectorized stores ----
    const int col0 = bn * BN + tx * TN;
    float bf[TN];
    #pragma unroll
    for (int j = 0; j < TN; j += 4) {
        float4 v = *(const float4*)(bias + col0 + j);
        bf[j + 0] = v.x; bf[j + 1] = v.y; bf[j + 2] = v.z; bf[j + 3] = v.w;
    }

    #pragma unroll
    for (int i = 0; i < TM; i++) {
        int row = bm * BM + ty * TM + i;
        float* out = C + (size_t)row * N + col0;
        #pragma unroll
        for (int j = 0; j < TN; j += 4) {
            float4 v;
            v.x = acc[i][j + 0] + bf[j + 0];
            v.y = acc[i][j + 1] + bf[j + 1];
            v.z = acc[i][j + 2] + bf[j + 2];
            v.w = acc[i][j + 3] + bf[j + 3];
            *(float4*)(out + j) = v;
        }
    }
}

extern "C" void kernel_launch(void* const* d_in, const int* in_sizes, int n_in,
                              void* d_out, int out_size)
{
    const float* A    = (const float*)d_in[0];   // input  [M,K]
    const int*   Q    = (const int*)  d_in[1];   // q_weights [N,K]
    const float* S    = (const float*)d_in[2];   // q_scales  [N,NB]
    const int*   Z    = (const int*)  d_in[3];   // q_zp      [N,NB]
    const float* bias = (const float*)d_in[4];   // [N]
    float*       C    = (float*)d_out;           // [M,N]

    const int N  = in_sizes[4];
    const int K  = in_sizes[1] / N;
    const int M  = in_sizes[0] / K;
    const int NB = in_sizes[2] / N;

    dim3 grid(N / BN, M / BM);
    dim3 block(256);
    blkq4_gemm_kernel<<<grid, block>>>(A, Q, S, Z, bias, C, M, N, K, NB);
}

// round 4
// speedup vs baseline: 2.8758x; 2.8758x over previous
#include <cuda_runtime.h>
#include <cstdint>

// Blockwise int4-dequant GEMM via tf32 tensor cores (mma.sync m16n8k8).
// out[m,n] = sum_k A[m,k] * (Q[n,k]-zp[n,k/64])*s[n,k/64] + bias[n]
// A: [M,K] f32; Q: [N,K] int32 in [0,16); S/Z: [N, K/64]; out: [M,N] f32.
//
// CTA tile 128x128x32, 256 threads = 8 warps in 2(M) x 4(N), warp tile 64x32.
// Per warp: 4x4 grid of m16n8k8 mma, K-loop 4 x k8 per CTA iteration.
// Dequant fused at smem store; operands stored pre-converted to tf32 (cvt.rna).
// Smem row stride 36 floats -> conflict-free fragment loads.

#define BM 128
#define BN 128
#define BK 32
#define SSTRIDE 36   // BK + 4 pad

__device__ __forceinline__ uint32_t f2tf32(float x) {
    uint32_t r;
    asm("cvt.rna.tf32.f32 %0, %1;" : "=r"(r) : "f"(x));
    return r;
}

__device__ __forceinline__ void mma_tf32(float& c0, float& c1, float& c2, float& c3,
                                         uint32_t a0, uint32_t a1, uint32_t a2, uint32_t a3,
                                         uint32_t b0, uint32_t b1) {
    asm volatile("mma.sync.aligned.m16n8k8.row.col.f32.tf32.tf32.f32 "
                 "{%0,%1,%2,%3}, {%4,%5,%6,%7}, {%8,%9}, {%0,%1,%2,%3};\n"
                 : "+f"(c0), "+f"(c1), "+f"(c2), "+f"(c3)
                 : "r"(a0), "r"(a1), "r"(a2), "r"(a3), "r"(b0), "r"(b1));
}

__global__ __launch_bounds__(256)
void blkq4_tf32_kernel(const float* __restrict__ A,
                       const int*   __restrict__ Q,
                       const float* __restrict__ S,
                       const int*   __restrict__ Z,
                       const float* __restrict__ bias,
                       float* __restrict__ C,
                       int M, int N, int K, int NB)
{
    __shared__ uint32_t As[BM * SSTRIDE];  // tf32-formatted A, [m][k]
    __shared__ uint32_t Ws[BN * SSTRIDE];  // tf32-formatted dequantized W, [n][k]

    const int tid  = threadIdx.x;
    const int lane = tid & 31;
    const int wid  = tid >> 5;
    const int warp_m = wid & 1;   // 0..1 -> 64-row half
    const int warp_n = wid >> 1;  // 0..3 -> 32-col slice
    const int gid = lane >> 2;    // group id 0..7
    const int tig = lane & 3;     // thread-in-group 0..3

    const int bn = blockIdx.x;
    const int bm = blockIdx.y;

    const float* Ablk = A + (size_t)bm * BM * K;
    const int*   Qblk = Q + (size_t)bn * BN * K;

    float acc[4][4][4];
    #pragma unroll
    for (int mi = 0; mi < 4; mi++)
        #pragma unroll
        for (int ni = 0; ni < 4; ni++)
            #pragma unroll
            for (int r = 0; r < 4; r++) acc[mi][ni][r] = 0.0f;

    // global-load slot mapping: 1024 float4/int4 slots per tile, 4 per thread
    // slot id = tid + i*256; row = id>>3 (0..127), col4 = (id&7)*4
    for (int k0 = 0; k0 < K; k0 += BK) {
        const int kb = k0 >> 6;  // quant block (64 wide) constant per 32-tile

        float4 aReg[4];
        int4   qReg[4];
        float  sReg[4], zReg[4];
        #pragma unroll
        for (int i = 0; i < 4; i++) {
            int id = tid + i * 256;
            int r  = id >> 3;
            int c4 = (id & 7) << 2;
            aReg[i] = *(const float4*)(Ablk + (size_t)r * K + k0 + c4);
            qReg[i] = *(const int4*)  (Qblk + (size_t)r * K + k0 + c4);
            int gn  = bn * BN + r;
            sReg[i] = S[(size_t)gn * NB + kb];
            zReg[i] = (float)Z[(size_t)gn * NB + kb];
        }

        __syncthreads();  // previous compute done before overwriting smem

        #pragma unroll
        for (int i = 0; i < 4; i++) {
            int id = tid + i * 256;
            int r  = id >> 3;
            int c4 = (id & 7) << 2;
            uint4 av;
            av.x = f2tf32(aReg[i].x);
            av.y = f2tf32(aReg[i].y);
            av.z = f2tf32(aReg[i].z);
            av.w = f2tf32(aReg[i].w);
            *(uint4*)(&As[r * SSTRIDE + c4]) = av;

            float s = sReg[i], zp = zReg[i];
            uint4 wv;
            wv.x = f2tf32(((float)qReg[i].x - zp) * s);
            wv.y = f2tf32(((float)qReg[i].y - zp) * s);
            wv.z = f2tf32(((float)qReg[i].z - zp) * s);
            wv.w = f2tf32(((float)qReg[i].w - zp) * s);
            *(uint4*)(&Ws[r * SSTRIDE + c4]) = wv;
        }

        __syncthreads();

        // compute: 4 k8 steps
        #pragma unroll
        for (int kk = 0; kk < 4; kk++) {
            const int kc = kk * 8 + tig;

            uint32_t af[4][4];
            #pragma unroll
            for (int mi = 0; mi < 4; mi++) {
                int rA = warp_m * 64 + mi * 16 + gid;
                af[mi][0] = As[rA * SSTRIDE + kc];
                af[mi][1] = As[(rA + 8) * SSTRIDE + kc];
                af[mi][2] = As[rA * SSTRIDE + kc + 4];
                af[mi][3] = As[(rA + 8) * SSTRIDE + kc + 4];
            }
            uint32_t bf[4][2];
            #pragma unroll
            for (int ni = 0; ni < 4; ni++) {
                int nB = warp_n * 32 + ni * 8 + gid;
                bf[ni][0] = Ws[nB * SSTRIDE + kc];
                bf[ni][1] = Ws[nB * SSTRIDE + kc + 4];
            }

            #pragma unroll
            for (int mi = 0; mi < 4; mi++)
                #pragma unroll
                for (int ni = 0; ni < 4; ni++)
                    mma_tf32(acc[mi][ni][0], acc[mi][ni][1], acc[mi][ni][2], acc[mi][ni][3],
                             af[mi][0], af[mi][1], af[mi][2], af[mi][3],
                             bf[ni][0], bf[ni][1]);
        }

        __syncthreads();
    }

    // epilogue: C layout per mma: c0,c1 at (row, 2*tig+{0,1}), c2,c3 at row+8
    #pragma unroll
    for (int mi = 0; mi < 4; mi++) {
        int row0 = bm * BM + warp_m * 64 + mi * 16 + gid;
        #pragma unroll
        for (int ni = 0; ni < 4; ni++) {
            int col = bn * BN + warp_n * 32 + ni * 8 + tig * 2;
            float2 bv = *(const float2*)(bias + col);
            float2 v0, v1;
            v0.x = acc[mi][ni][0] + bv.x;
            v0.y = acc[mi][ni][1] + bv.y;
            v1.x = acc[mi][ni][2] + bv.x;
            v1.y = acc[mi][ni][3] + bv.y;
            *(float2*)(C + (size_t)row0 * N + col)       = v0;
            *(float2*)(C + (size_t)(row0 + 8) * N + col) = v1;
        }
    }
}

extern "C" void kernel_launch(void* const* d_in, const int* in_sizes, int n_in,
                              void* d_out, int out_size)
{
    const float* A    = (const float*)d_in[0];   // input  [M,K]
    const int*   Q    = (const int*)  d_in[1];   // q_weights [N,K]
    const float* S    = (const float*)d_in[2];   // q_scales  [N,NB]
    const int*   Z    = (const int*)  d_in[3];   // q_zp      [N,NB]
    const float* bias = (const float*)d_in[4];   // [N]
    float*       C    = (float*)d_out;           // [M,N]

    const int N  = in_sizes[4];
    const int K  = in_sizes[1] / N;
    const int M  = in_sizes[0] / K;
    const int NB = in_sizes[2] / N;

    dim3 grid(N / BN, M / BM);
    dim3 block(256);
    blkq4_tf32_kernel<<<grid, block>>>(A, Q, S, Z, bias, C, M, N, K, NB);
}

// round 6
// speedup vs baseline: 4.2363x; 1.4731x over previous
#include <cuda_runtime.h>
#include <cstdint>

// Blockwise int4-dequant GEMM, tf32 mma.sync path (tcgen05 unavailable:
// harness compiles to .target sm_103 without the 'a' feature set).
//
// Phase 1 (prep kernels): A[f32] -> gA[tf32] (cvt.rna), and
// W = (Q - zp)*s -> gW[tf32]. Both in __device__ global scratch.
// Phase 2 (GEMM): pure tf32 mma.sync m16n8k8, 128x128x32 CTA tile,
// 8 warps (2Mx4N), warp tile 64x32, 3-stage cp.async.cg smem pipeline.

#define M_DIM 4096
#define K_DIM 4096
#define N_DIM 11008

__device__ uint32_t gA[(size_t)M_DIM * K_DIM];   // tf32 A, row-major [M,K]
__device__ uint32_t gW[(size_t)N_DIM * K_DIM];   // tf32 dequant W, row-major [N,K]

#define BM 128
#define BN 128
#define BK 32
#define SSTRIDE 36                    // words per smem row (BK + 4 pad)
#define STAGES 3
#define STAGE_WORDS (2 * BM * SSTRIDE)     // A + W per stage
#define SMEM_BYTES (STAGES * STAGE_WORDS * 4)

__device__ __forceinline__ uint32_t f2tf32(float x) {
    uint32_t r; asm("cvt.rna.tf32.f32 %0, %1;" : "=r"(r) : "f"(x)); return r;
}

__device__ __forceinline__ void mma_tf32(float& c0, float& c1, float& c2, float& c3,
                                         uint32_t a0, uint32_t a1, uint32_t a2, uint32_t a3,
                                         uint32_t b0, uint32_t b1) {
    asm volatile("mma.sync.aligned.m16n8k8.row.col.f32.tf32.tf32.f32 "
                 "{%0,%1,%2,%3}, {%4,%5,%6,%7}, {%8,%9}, {%0,%1,%2,%3};\n"
                 : "+f"(c0), "+f"(c1), "+f"(c2), "+f"(c3)
                 : "r"(a0), "r"(a1), "r"(a2), "r"(a3), "r"(b0), "r"(b1));
}

#define CP_ASYNC16(dst, src) \
    asm volatile("cp.async.cg.shared.global [%0], [%1], 16;" :: "r"(dst), "l"(src))
#define CP_COMMIT()  asm volatile("cp.async.commit_group;" ::: "memory")
#define CP_WAIT(n)   asm volatile("cp.async.wait_group %0;" :: "n"(n) : "memory")

// ---------------- prep kernels ----------------

__global__ __launch_bounds__(256)
void prep_a_kernel(const float* __restrict__ A, size_t total4)
{
    size_t e = (size_t)blockIdx.x * 256 + threadIdx.x;
    if (e >= total4) return;
    float4 v = *(const float4*)(A + e * 4);
    uint4 o;
    o.x = f2tf32(v.x); o.y = f2tf32(v.y); o.z = f2tf32(v.z); o.w = f2tf32(v.w);
    *(uint4*)(gA + e * 4) = o;
}

__global__ __launch_bounds__(256)
void prep_w_kernel(const int* __restrict__ Q,
                   const float* __restrict__ S,
                   const int* __restrict__ Z,
                   int K, int NB, size_t total4)
{
    size_t e = (size_t)blockIdx.x * 256 + threadIdx.x;
    if (e >= total4) return;
    size_t base = e * 4;
    int n  = (int)(base / K);
    int k  = (int)(base % K);
    int kb = k >> 6;                       // BLOCK_SIZE=64; 4 consecutive k share kb
    float s  = S[(size_t)n * NB + kb];
    float nz = -(float)Z[(size_t)n * NB + kb] * s;
    int4 q = *(const int4*)(Q + base);
    uint4 o;
    o.x = f2tf32(fmaf((float)q.x, s, nz));
    o.y = f2tf32(fmaf((float)q.y, s, nz));
    o.z = f2tf32(fmaf((float)q.z, s, nz));
    o.w = f2tf32(fmaf((float)q.w, s, nz));
    *(uint4*)(gW + base) = o;
}

// ---------------- GEMM kernel ----------------

__global__ __launch_bounds__(256, 2)
void blkq4_gemm_tf32(const float* __restrict__ bias,
                     float* __restrict__ C,
                     int M, int N, int K)
{
    extern __shared__ uint32_t smem[];

    const int tid  = threadIdx.x;
    const int lane = tid & 31;
    const int wid  = tid >> 5;
    const int warp_m = wid & 1;   // 0..1 -> 64-row half
    const int warp_n = wid >> 1;  // 0..3 -> 32-col slice
    const int gid = lane >> 2;
    const int tig = lane & 3;

    const int bn = blockIdx.x;
    const int bm = blockIdx.y;

    const uint32_t* Ablk = gA + (size_t)bm * BM * K;
    const uint32_t* Wblk = gW + (size_t)bn * BN * K;

    const uint32_t sbase = (uint32_t)__cvta_generic_to_shared(smem);

    // per-thread cp.async slots: id = tid + i*256; r = id>>3; c4 = (id&7)*4
    const int r_ld[4]  = { (tid + 0) >> 3, (tid + 256) >> 3, (tid + 512) >> 3, (tid + 768) >> 3 };
    const int c4_ld    = (tid & 7) << 2;

    float acc[4][4][4];
    #pragma unroll
    for (int mi = 0; mi < 4; mi++)
        #pragma unroll
        for (int ni = 0; ni < 4; ni++)
            #pragma unroll
            for (int r = 0; r < 4; r++) acc[mi][ni][r] = 0.0f;

    const int T = K / BK;  // 128

    // ---- prologue: fill stages 0..STAGES-2 ----
    #pragma unroll
    for (int t = 0; t < STAGES - 1; t++) {
        const uint32_t aS = sbase + (t * STAGE_WORDS) * 4;
        const uint32_t wS = aS + (BM * SSTRIDE) * 4;
        const int k0 = t * BK;
        #pragma unroll
        for (int i = 0; i < 4; i++) {
            int r = r_ld[i];
            uint32_t doff = (uint32_t)(r * SSTRIDE + c4_ld) * 4;
            CP_ASYNC16(aS + doff, Ablk + (size_t)r * K + k0 + c4_ld);
            CP_ASYNC16(wS + doff, Wblk + (size_t)r * K + k0 + c4_ld);
        }
        CP_COMMIT();
    }

    for (int t = 0; t < T; t++) {
        CP_WAIT(STAGES - 2);          // tile t resident
        __syncthreads();

        const int sc = t % STAGES;
        const uint32_t* As = smem + sc * STAGE_WORDS;
        const uint32_t* Ws = As + BM * SSTRIDE;

        // ---- compute: 4 k8 steps, 16 mma each ----
        #pragma unroll
        for (int kk = 0; kk < 4; kk++) {
            const int kc = kk * 8 + tig;

            uint32_t af[4][4];
            #pragma unroll
            for (int mi = 0; mi < 4; mi++) {
                int rA = warp_m * 64 + mi * 16 + gid;
                af[mi][0] = As[rA * SSTRIDE + kc];
                af[mi][1] = As[(rA + 8) * SSTRIDE + kc];
                af[mi][2] = As[rA * SSTRIDE + kc + 4];
                af[mi][3] = As[(rA + 8) * SSTRIDE + kc + 4];
            }
            uint32_t bf[4][2];
            #pragma unroll
            for (int ni = 0; ni < 4; ni++) {
                int nB = warp_n * 32 + ni * 8 + gid;
                bf[ni][0] = Ws[nB * SSTRIDE + kc];
                bf[ni][1] = Ws[nB * SSTRIDE + kc + 4];
            }

            #pragma unroll
            for (int mi = 0; mi < 4; mi++)
                #pragma unroll
                for (int ni = 0; ni < 4; ni++)
                    mma_tf32(acc[mi][ni][0], acc[mi][ni][1], acc[mi][ni][2], acc[mi][ni][3],
                             af[mi][0], af[mi][1], af[mi][2], af[mi][3],
                             bf[ni][0], bf[ni][1]);
        }

        __syncthreads();              // stage sc free for refill

        // ---- issue load for tile t+STAGES-1 into stage (t-1)%STAGES ----
        const int tl = t + STAGES - 1;
        if (tl < T) {
            const int sl = tl % STAGES;
            const uint32_t aS = sbase + (sl * STAGE_WORDS) * 4;
            const uint32_t wS = aS + (BM * SSTRIDE) * 4;
            const int k0 = tl * BK;
            #pragma unroll
            for (int i = 0; i < 4; i++) {
                int r = r_ld[i];
                uint32_t doff = (uint32_t)(r * SSTRIDE + c4_ld) * 4;
                CP_ASYNC16(aS + doff, Ablk + (size_t)r * K + k0 + c4_ld);
                CP_ASYNC16(wS + doff, Wblk + (size_t)r * K + k0 + c4_ld);
            }
        }
        CP_COMMIT();                  // one group per iteration, possibly empty
    }

    // ---- epilogue ----
    #pragma unroll
    for (int mi = 0; mi < 4; mi++) {
        int row0 = bm * BM + warp_m * 64 + mi * 16 + gid;
        #pragma unroll
        for (int ni = 0; ni < 4; ni++) {
            int col = bn * BN + warp_n * 32 + ni * 8 + tig * 2;
            float2 bv = *(const float2*)(bias + col);
            float2 v0, v1;
            v0.x = acc[mi][ni][0] + bv.x;
            v0.y = acc[mi][ni][1] + bv.y;
            v1.x = acc[mi][ni][2] + bv.x;
            v1.y = acc[mi][ni][3] + bv.y;
            *(float2*)(C + (size_t)row0 * N + col)       = v0;
            *(float2*)(C + (size_t)(row0 + 8) * N + col) = v1;
        }
    }
}

extern "C" void kernel_launch(void* const* d_in, const int* in_sizes, int n_in,
                              void* d_out, int out_size)
{
    const float* A    = (const float*)d_in[0];   // input  [M,K]
    const int*   Q    = (const int*)  d_in[1];   // q_weights [N,K]
    const float* S    = (const float*)d_in[2];   // q_scales  [N,NB]
    const int*   Z    = (const int*)  d_in[3];   // q_zp      [N,NB]
    const float* bias = (const float*)d_in[4];   // [N]
    float*       C    = (float*)d_out;           // [M,N]

    const int N  = in_sizes[4];
    const int K  = in_sizes[1] / N;
    const int M  = in_sizes[0] / K;
    const int NB = in_sizes[2] / N;

    // prep: A -> tf32, W -> dequant tf32
    size_t a4 = (size_t)M * K / 4;
    size_t w4 = (size_t)N * K / 4;
    prep_a_kernel<<<(unsigned)((a4 + 255) / 256), 256>>>(A, a4);
    prep_w_kernel<<<(unsigned)((w4 + 255) / 256), 256>>>(Q, S, Z, K, NB, w4);

    cudaFuncSetAttribute(blkq4_gemm_tf32,
                         cudaFuncAttributeMaxDynamicSharedMemorySize, SMEM_BYTES);

    dim3 grid(N / BN, M / BM);
    blkq4_gemm_tf32<<<grid, 256, SMEM_BYTES>>>(bias, C, M, N, K);
}

// round 9
// speedup vs baseline: 6.6413x; 1.5677x over previous
#include <cuda_runtime.h>
#include <cuda_fp16.h>
#include <cstdint>

// Blockwise int4-dequant GEMM, fp16 mma.sync m16n8k16 path.
// fp16 has the same 10-bit mantissa as tf32 (products exact in f32 accum),
// so accuracy matches the tf32 kernel (~2.9e-4) at half the bytes/FLOP and
// half the tensor instruction count.
//
// Phase 1: prep kernels convert A -> fp16 and W=(Q-zp)*s -> fp16 into global
// scratch. Phase 2: pure fp16 GEMM, 128x128x32 CTA tile, 8 warps (2Mx4N),
// warp tile 64x32, 4-stage cp.async.cg pipeline, conflict-free smem (stride
// 20 words of packed half2).

#define M_DIM 4096
#define K_DIM 4096
#define N_DIM 11008

__device__ uint32_t gA[(size_t)M_DIM * K_DIM / 2];   // half2-packed A [M, K/2]
__device__ uint32_t gW[(size_t)N_DIM * K_DIM / 2];   // half2-packed W [N, K/2]

#define BM 128
#define BN 128
#define BK 32                        // k elements per tile (16 half2 words)
#define KW 16                        // words per row per tile
#define SSTRIDE 20                   // words per smem row (16 + 4 pad)
#define STAGES 4
#define STAGE_WORDS (2 * BM * SSTRIDE)
#define SMEM_BYTES (STAGES * STAGE_WORDS * 4)

// pack two floats -> one u32 of fp16x2 (rn)
__device__ __forceinline__ uint32_t pack_h2(float lo, float hi) {
    uint32_t r;
    asm("{\n\t.reg .f16 l, h;\n\t"
        "cvt.rn.f16.f32 l, %1;\n\t"
        "cvt.rn.f16.f32 h, %2;\n\t"
        "mov.b32 %0, {l, h};\n\t}"
        : "=r"(r) : "f"(lo), "f"(hi));
    return r;
}

__device__ __forceinline__ void mma_f16(float& c0, float& c1, float& c2, float& c3,
                                        uint32_t a0, uint32_t a1, uint32_t a2, uint32_t a3,
                                        uint32_t b0, uint32_t b1) {
    asm volatile("mma.sync.aligned.m16n8k16.row.col.f32.f16.f16.f32 "
                 "{%0,%1,%2,%3}, {%4,%5,%6,%7}, {%8,%9}, {%0,%1,%2,%3};\n"
                 : "+f"(c0), "+f"(c1), "+f"(c2), "+f"(c3)
                 : "r"(a0), "r"(a1), "r"(a2), "r"(a3), "r"(b0), "r"(b1));
}

#define CP_ASYNC16(dst, src) \
    asm volatile("cp.async.cg.shared.global [%0], [%1], 16;" :: "r"(dst), "l"(src))
#define CP_COMMIT()  asm volatile("cp.async.commit_group;" ::: "memory")
#define CP_WAIT(n)   asm volatile("cp.async.wait_group %0;" :: "n"(n) : "memory")

// ---------------- prep kernels ----------------

__global__ __launch_bounds__(256)
void prep_a_kernel(const float* __restrict__ A, size_t total4)
{
    size_t e = (size_t)blockIdx.x * 256 + threadIdx.x;
    if (e >= total4) return;
    float4 v = *(const float4*)(A + e * 4);
    uint2 o;
    o.x = pack_h2(v.x, v.y);
    o.y = pack_h2(v.z, v.w);
    *(uint2*)(gA + e * 2) = o;
}

__global__ __launch_bounds__(256)
void prep_w_kernel(const int* __restrict__ Q,
                   const float* __restrict__ S,
                   const int* __restrict__ Z,
                   int K, int NB, size_t total4)
{
    size_t e = (size_t)blockIdx.x * 256 + threadIdx.x;
    if (e >= total4) return;
    size_t base = e * 4;
    int n  = (int)(base / K);
    int k  = (int)(base % K);
    int kb = k >> 6;                 // BLOCK_SIZE=64; 4 consecutive k share kb
    float s  = S[(size_t)n * NB + kb];
    float nz = -(float)Z[(size_t)n * NB + kb] * s;
    int4 q = *(const int4*)(Q + base);
    uint2 o;
    o.x = pack_h2(fmaf((float)q.x, s, nz), fmaf((float)q.y, s, nz));
    o.y = pack_h2(fmaf((float)q.z, s, nz), fmaf((float)q.w, s, nz));
    *(uint2*)(gW + e * 2) = o;
}

// ---------------- GEMM kernel ----------------

__global__ __launch_bounds__(256, 2)
void blkq4_gemm_f16(const float* __restrict__ bias,
                    float* __restrict__ C,
                    int M, int N, int K)
{
    extern __shared__ uint32_t smem[];

    const int tid  = threadIdx.x;
    const int lane = tid & 31;
    const int wid  = tid >> 5;
    const int warp_m = wid & 1;   // 0..1 -> 64-row half
    const int warp_n = wid >> 1;  // 0..3 -> 32-col slice
    const int gid = lane >> 2;    // 0..7
    const int tig = lane & 3;     // 0..3

    const int bn = blockIdx.x;
    const int bm = blockIdx.y;

    const int Kw = K / 2;         // row stride of gA/gW in words
    const uint32_t* Ablk = gA + (size_t)bm * BM * Kw;
    const uint32_t* Wblk = gW + (size_t)bn * BN * Kw;

    const uint32_t sbase = (uint32_t)__cvta_generic_to_shared(smem);

    // cp.async slots: 128 rows x 4 chunks(16B) per operand = 512; 2/thread.
    // id = tid + i*256: r = id>>2, chunk word col = (id&3)*4
    const int r_ld[2] = { tid >> 2, (tid + 256) >> 2 };
    const int cw_ld   = (tid & 3) << 2;

    float acc[4][4][4];
    #pragma unroll
    for (int mi = 0; mi < 4; mi++)
        #pragma unroll
        for (int ni = 0; ni < 4; ni++)
            #pragma unroll
            for (int r = 0; r < 4; r++) acc[mi][ni][r] = 0.0f;

    const int T = K / BK;         // 128 tiles

    // ---- prologue: fill stages 0..STAGES-2 ----
    #pragma unroll
    for (int t = 0; t < STAGES - 1; t++) {
        const uint32_t aS = sbase + (t * STAGE_WORDS) * 4;
        const uint32_t wS = aS + (BM * SSTRIDE) * 4;
        const int k0w = t * KW;
        #pragma unroll
        for (int i = 0; i < 2; i++) {
            int r = r_ld[i];
            uint32_t doff = (uint32_t)(r * SSTRIDE + cw_ld) * 4;
            CP_ASYNC16(aS + doff, Ablk + (size_t)r * Kw + k0w + cw_ld);
            CP_ASYNC16(wS + doff, Wblk + (size_t)r * Kw + k0w + cw_ld);
        }
        CP_COMMIT();
    }

    for (int t = 0; t < T; t++) {
        CP_WAIT(STAGES - 2);
        __syncthreads();

        const int sc = t % STAGES;
        const uint32_t* As = smem + sc * STAGE_WORDS;
        const uint32_t* Ws = As + BM * SSTRIDE;

        // ---- compute: 2 x k16 steps ----
        #pragma unroll
        for (int kk = 0; kk < 2; kk++) {
            const int kc = kk * 8 + tig;   // half2-word col within row

            uint32_t af[4][4];
            #pragma unroll
            for (int mi = 0; mi < 4; mi++) {
                int rA = warp_m * 64 + mi * 16 + gid;
                af[mi][0] = As[rA * SSTRIDE + kc];
                af[mi][1] = As[(rA + 8) * SSTRIDE + kc];
                af[mi][2] = As[rA * SSTRIDE + kc + 4];
                af[mi][3] = As[(rA + 8) * SSTRIDE + kc + 4];
            }
            uint32_t bf[4][2];
            #pragma unroll
            for (int ni = 0; ni < 4; ni++) {
                int nB = warp_n * 32 + ni * 8 + gid;
                bf[ni][0] = Ws[nB * SSTRIDE + kc];
                bf[ni][1] = Ws[nB * SSTRIDE + kc + 4];
            }

            #pragma unroll
            for (int mi = 0; mi < 4; mi++)
                #pragma unroll
                for (int ni = 0; ni < 4; ni++)
                    mma_f16(acc[mi][ni][0], acc[mi][ni][1], acc[mi][ni][2], acc[mi][ni][3],
                            af[mi][0], af[mi][1], af[mi][2], af[mi][3],
                            bf[ni][0], bf[ni][1]);
        }

        __syncthreads();

        // ---- refill: tile t+STAGES-1 into stage (t+STAGES-1)%STAGES ----
        const int tl = t + STAGES - 1;
        if (tl < T) {
            const int sl = tl % STAGES;
            const uint32_t aS = sbase + (sl * STAGE_WORDS) * 4;
            const uint32_t wS = aS + (BM * SSTRIDE) * 4;
            const int k0w = tl * KW;
            #pragma unroll
            for (int i = 0; i < 2; i++) {
                int r = r_ld[i];
                uint32_t doff = (uint32_t)(r * SSTRIDE + cw_ld) * 4;
                CP_ASYNC16(aS + doff, Ablk + (size_t)r * Kw + k0w + cw_ld);
                CP_ASYNC16(wS + doff, Wblk + (size_t)r * Kw + k0w + cw_ld);
            }
        }
        CP_COMMIT();
    }

    // ---- epilogue ----
    #pragma unroll
    for (int mi = 0; mi < 4; mi++) {
        int row0 = bm * BM + warp_m * 64 + mi * 16 + gid;
        #pragma unroll
        for (int ni = 0; ni < 4; ni++) {
            int col = bn * BN + warp_n * 32 + ni * 8 + tig * 2;
            float2 bv = *(const float2*)(bias + col);
            float2 v0, v1;
            v0.x = acc[mi][ni][0] + bv.x;
            v0.y = acc[mi][ni][1] + bv.y;
            v1.x = acc[mi][ni][2] + bv.x;
            v1.y = acc[mi][ni][3] + bv.y;
            *(float2*)(C + (size_t)row0 * N + col)       = v0;
            *(float2*)(C + (size_t)(row0 + 8) * N + col) = v1;
        }
    }
}

extern "C" void kernel_launch(void* const* d_in, const int* in_sizes, int n_in,
                              void* d_out, int out_size)
{
    const float* A    = (const float*)d_in[0];   // input  [M,K]
    const int*   Q    = (const int*)  d_in[1];   // q_weights [N,K]
    const float* S    = (const float*)d_in[2];   // q_scales  [N,NB]
    const int*   Z    = (const int*)  d_in[3];   // q_zp      [N,NB]
    const float* bias = (const float*)d_in[4];   // [N]
    float*       C    = (float*)d_out;           // [M,N]

    const int N  = in_sizes[4];
    const int K  = in_sizes[1] / N;
    const int M  = in_sizes[0] / K;
    const int NB = in_sizes[2] / N;

    size_t a4 = (size_t)M * K / 4;
    size_t w4 = (size_t)N * K / 4;
    prep_a_kernel<<<(unsigned)((a4 + 255) / 256), 256>>>(A, a4);
    prep_w_kernel<<<(unsigned)((w4 + 255) / 256), 256>>>(Q, S, Z, K, NB, w4);

    cudaFuncSetAttribute(blkq4_gemm_f16,
                         cudaFuncAttributeMaxDynamicSharedMemorySize, SMEM_BYTES);

    dim3 grid(N / BN, M / BM);
    blkq4_gemm_f16<<<grid, 256, SMEM_BYTES>>>(bias, C, M, N, K);
}

// round 10
// speedup vs baseline: 6.7980x; 1.0236x over previous
#include <cuda_runtime.h>
#include <cuda_fp16.h>
#include <cstdint>

// Blockwise int4-dequant GEMM, fp16 mma.sync m16n8k16 + ldmatrix.x4.
// Phase 1: prep A -> fp16, W=(Q-zp)*s -> fp16 (global scratch).
// Phase 2: fp16 GEMM, 128x128x32 CTA tile, 8 warps (2Mx4N), warp tile 64x32,
// 4-stage cp.async.cg pipeline, ONE __syncthreads per tile, all fragment
// loads via ldmatrix.sync.aligned.m8n8.x4 (conflict-free on stride-20 rows).

#define M_DIM 4096
#define K_DIM 4096
#define N_DIM 11008

__device__ uint32_t gA[(size_t)M_DIM * K_DIM / 2];   // half2-packed A [M, K/2]
__device__ uint32_t gW[(size_t)N_DIM * K_DIM / 2];   // half2-packed W [N, K/2]

#define BM 128
#define BN 128
#define BK 32                        // k elements per tile (16 half2 words)
#define KW 16                        // words per row per tile
#define SSTRIDE 20                   // words per smem row (16 + 4 pad)
#define STAGES 4
#define STAGE_WORDS (2 * BM * SSTRIDE)
#define SMEM_BYTES (STAGES * STAGE_WORDS * 4)

__device__ __forceinline__ uint32_t pack_h2(float lo, float hi) {
    uint32_t r;
    asm("{\n\t.reg .f16 l, h;\n\t"
        "cvt.rn.f16.f32 l, %1;\n\t"
        "cvt.rn.f16.f32 h, %2;\n\t"
        "mov.b32 %0, {l, h};\n\t}"
        : "=r"(r) : "f"(lo), "f"(hi));
    return r;
}

__device__ __forceinline__ void mma_f16(float& c0, float& c1, float& c2, float& c3,
                                        uint32_t a0, uint32_t a1, uint32_t a2, uint32_t a3,
                                        uint32_t b0, uint32_t b1) {
    asm volatile("mma.sync.aligned.m16n8k16.row.col.f32.f16.f16.f32 "
                 "{%0,%1,%2,%3}, {%4,%5,%6,%7}, {%8,%9}, {%0,%1,%2,%3};\n"
                 : "+f"(c0), "+f"(c1), "+f"(c2), "+f"(c3)
                 : "r"(a0), "r"(a1), "r"(a2), "r"(a3), "r"(b0), "r"(b1));
}

#define LDSM_X4(r0, r1, r2, r3, addr)                                        \
    asm volatile("ldmatrix.sync.aligned.m8n8.x4.shared.b16 {%0,%1,%2,%3}, [%4];" \
                 : "=r"(r0), "=r"(r1), "=r"(r2), "=r"(r3) : "r"(addr))

#define CP_ASYNC16(dst, src) \
    asm volatile("cp.async.cg.shared.global [%0], [%1], 16;" :: "r"(dst), "l"(src))
#define CP_COMMIT()  asm volatile("cp.async.commit_group;" ::: "memory")
#define CP_WAIT(n)   asm volatile("cp.async.wait_group %0;" :: "n"(n) : "memory")

// ---------------- prep kernels ----------------

__global__ __launch_bounds__(256)
void prep_a_kernel(const float* __restrict__ A, size_t total4)
{
    size_t e = (size_t)blockIdx.x * 256 + threadIdx.x;
    if (e >= total4) return;
    float4 v = *(const float4*)(A + e * 4);
    uint2 o;
    o.x = pack_h2(v.x, v.y);
    o.y = pack_h2(v.z, v.w);
    *(uint2*)(gA + e * 2) = o;
}

__global__ __launch_bounds__(256)
void prep_w_kernel(const int* __restrict__ Q,
                   const float* __restrict__ S,
                   const int* __restrict__ Z,
                   int K, int NB, size_t total4)
{
    size_t e = (size_t)blockIdx.x * 256 + threadIdx.x;
    if (e >= total4) return;
    size_t base = e * 4;
    int n  = (int)(base / K);
    int k  = (int)(base % K);
    int kb = k >> 6;                 // BLOCK_SIZE=64; 4 consecutive k share kb
    float s  = S[(size_t)n * NB + kb];
    float nz = -(float)Z[(size_t)n * NB + kb] * s;
    int4 q = *(const int4*)(Q + base);
    uint2 o;
    o.x = pack_h2(fmaf((float)q.x, s, nz), fmaf((float)q.y, s, nz));
    o.y = pack_h2(fmaf((float)q.z, s, nz), fmaf((float)q.w, s, nz));
    *(uint2*)(gW + e * 2) = o;
}

// ---------------- GEMM kernel ----------------

__global__ __launch_bounds__(256, 2)
void blkq4_gemm_f16(const float* __restrict__ bias,
                    float* __restrict__ C,
                    int M, int N, int K)
{
    extern __shared__ uint32_t smem[];

    const int tid  = threadIdx.x;
    const int lane = tid & 31;
    const int wid  = tid >> 5;
    const int warp_m = wid & 1;   // 0..1 -> 64-row half
    const int warp_n = wid >> 1;  // 0..3 -> 32-col slice
    const int gid = lane >> 2;    // 0..7
    const int tig = lane & 3;     // 0..3

    const int bn = blockIdx.x;
    const int bm = blockIdx.y;

    const int Kw = K / 2;         // row stride of gA/gW in words
    const uint32_t* Ablk = gA + (size_t)bm * BM * Kw;
    const uint32_t* Wblk = gW + (size_t)bn * BN * Kw;

    const uint32_t sbase = (uint32_t)__cvta_generic_to_shared(smem);

    // cp.async slots: id = tid + i*256: r = id>>2, word col = (id&3)*4
    const int r_ld[2] = { tid >> 2, (tid + 256) >> 2 };
    const int cw_ld   = (tid & 3) << 2;

    // ldmatrix per-lane addressing: 4 matrices per x4:
    //   lanes 0-7: (lo-rows, k-lo), 8-15: (hi-rows, k-lo),
    //   16-23: (lo-rows, k-hi), 24-31: (hi-rows, k-hi)
    const int lrow  = lane & 15;               // row within 16-row group
    const int lcolw = (lane >> 4) << 2;        // +0 or +4 words (k-lo/k-hi)
    // A: base row = warp_m*64 + mi*16 ; B: base row = warp_n*32 + ni2*16
    uint32_t aOff[4], bOff[2];
    #pragma unroll
    for (int mi = 0; mi < 4; mi++)
        aOff[mi] = (uint32_t)(((warp_m * 64 + mi * 16 + lrow) * SSTRIDE + lcolw) * 4);
    #pragma unroll
    for (int n2 = 0; n2 < 2; n2++)
        bOff[n2] = (uint32_t)(((warp_n * 32 + n2 * 16 + lrow) * SSTRIDE + lcolw) * 4
                              + BM * SSTRIDE * 4);

    float acc[4][4][4];
    #pragma unroll
    for (int mi = 0; mi < 4; mi++)
        #pragma unroll
        for (int ni = 0; ni < 4; ni++)
            #pragma unroll
            for (int r = 0; r < 4; r++) acc[mi][ni][r] = 0.0f;

    const int T = K / BK;         // 128 tiles

    // ---- prologue: fill stages 0..STAGES-2 ----
    #pragma unroll
    for (int t = 0; t < STAGES - 1; t++) {
        const uint32_t aS = sbase + (t * STAGE_WORDS) * 4;
        const uint32_t wS = aS + (BM * SSTRIDE) * 4;
        const int k0w = t * KW;
        #pragma unroll
        for (int i = 0; i < 2; i++) {
            int r = r_ld[i];
            uint32_t doff = (uint32_t)(r * SSTRIDE + cw_ld) * 4;
            CP_ASYNC16(aS + doff, Ablk + (size_t)r * Kw + k0w + cw_ld);
            CP_ASYNC16(wS + doff, Wblk + (size_t)r * Kw + k0w + cw_ld);
        }
        CP_COMMIT();
    }

    for (int t = 0; t < T; t++) {
        CP_WAIT(STAGES - 2);          // tile t resident
        __syncthreads();              // all warps done with tile t-1 ldmatrix

        // ---- refill: tile t+STAGES-1 into stage (t+STAGES-1)%STAGES ----
        const int tl = t + STAGES - 1;
        if (tl < T) {
            const int sl = tl % STAGES;
            const uint32_t aS = sbase + (sl * STAGE_WORDS) * 4;
            const uint32_t wS = aS + (BM * SSTRIDE) * 4;
            const int k0w = tl * KW;
            #pragma unroll
            for (int i = 0; i < 2; i++) {
                int r = r_ld[i];
                uint32_t doff = (uint32_t)(r * SSTRIDE + cw_ld) * 4;
                CP_ASYNC16(aS + doff, Ablk + (size_t)r * Kw + k0w + cw_ld);
                CP_ASYNC16(wS + doff, Wblk + (size_t)r * Kw + k0w + cw_ld);
            }
        }
        CP_COMMIT();

        // ---- compute tile t from stage t%STAGES ----
        const uint32_t stg = sbase + ((t % STAGES) * STAGE_WORDS) * 4;

        #pragma unroll
        for (int kk = 0; kk < 2; kk++) {
            const uint32_t kb = stg + (uint32_t)(kk * 8 * 4);  // +kk*32 bytes

            uint32_t af[4][4];
            #pragma unroll
            for (int mi = 0; mi < 4; mi++)
                LDSM_X4(af[mi][0], af[mi][1], af[mi][2], af[mi][3], kb + aOff[mi]);

            uint32_t bf[4][2];
            #pragma unroll
            for (int n2 = 0; n2 < 2; n2++)
                LDSM_X4(bf[2 * n2][0], bf[2 * n2 + 1][0],
                        bf[2 * n2][1], bf[2 * n2 + 1][1], kb + bOff[n2]);

            #pragma unroll
            for (int mi = 0; mi < 4; mi++)
                #pragma unroll
                for (int ni = 0; ni < 4; ni++)
                    mma_f16(acc[mi][ni][0], acc[mi][ni][1], acc[mi][ni][2], acc[mi][ni][3],
                            af[mi][0], af[mi][1], af[mi][2], af[mi][3],
                            bf[ni][0], bf[ni][1]);
        }
    }

    // ---- epilogue ----
    #pragma unroll
    for (int mi = 0; mi < 4; mi++) {
        int row0 = bm * BM + warp_m * 64 + mi * 16 + gid;
        #pragma unroll
        for (int ni = 0; ni < 4; ni++) {
            int col = bn * BN + warp_n * 32 + ni * 8 + tig * 2;
            float2 bv = *(const float2*)(bias + col);
            float2 v0, v1;
            v0.x = acc[mi][ni][0] + bv.x;
            v0.y = acc[mi][ni][1] + bv.y;
            v1.x = acc[mi][ni][2] + bv.x;
            v1.y = acc[mi][ni][3] + bv.y;
            *(float2*)(C + (size_t)row0 * N + col)       = v0;
            *(float2*)(C + (size_t)(row0 + 8) * N + col) = v1;
        }
    }
}

extern "C" void kernel_launch(void* const* d_in, const int* in_sizes, int n_in,
                              void* d_out, int out_size)
{
    const float* A    = (const float*)d_in[0];   // input  [M,K]
    const int*   Q    = (const int*)  d_in[1];   // q_weights [N,K]
    const float* S    = (const float*)d_in[2];   // q_scales  [N,NB]
    const int*   Z    = (const int*)  d_in[3];   // q_zp      [N,NB]
    const float* bias = (const float*)d_in[4];   // [N]
    float*       C    = (float*)d_out;           // [M,N]

    const int N  = in_sizes[4];
    const int K  = in_sizes[1] / N;
    const int M  = in_sizes[0] / K;
    const int NB = in_sizes[2] / N;

    size_t a4 = (size_t)M * K / 4;
    size_t w4 = (size_t)N * K / 4;
    prep_a_kernel<<<(unsigned)((a4 + 255) / 256), 256>>>(A, a4);
    prep_w_kernel<<<(unsigned)((w4 + 255) / 256), 256>>>(Q, S, Z, K, NB, w4);

    cudaFuncSetAttribute(blkq4_gemm_f16,
                         cudaFuncAttributeMaxDynamicSharedMemorySize, SMEM_BYTES);

    dim3 grid(N / BN, M / BM);
    blkq4_gemm_f16<<<grid, 256, SMEM_BYTES>>>(bias, C, M, N, K);
}